// round 9
// baseline (speedup 1.0000x reference)
#include <cuda_runtime.h>
#include <cuda_bf16.h>
#include <cuda_fp16.h>
#include <math.h>
#include <stdint.h>

#define NB    4
#define S_LEN 4096
#define HID   2048
#define HD    128
#define NROWS (NB * S_LEN)          // 16384
#define LOG2E 1.4426950408889634f

// ---------------- scratch (no allocs allowed) ----------------
__device__ __nv_bfloat16 g_xhi[NROWS * HID];
__device__ __nv_bfloat16 g_xlo[NROWS * HID];
__device__ __nv_bfloat16 g_wthi[3 * HD * HID];   // [head][n][k] = W^T split hi
__device__ __nv_bfloat16 g_wtlo[3 * HD * HID];
__device__ __half g_qh[NROWS * HD];   // Q*log2e hi/lo fp16
__device__ __half g_ql[NROWS * HD];
__device__ __half g_kh[NROWS * HD];
__device__ __half g_kl[NROWS * HD];
__device__ __half g_vv[NROWS * HD];   // V fp16
__device__ int g_task;

// ======================= helpers =======================
__device__ __forceinline__ uint32_t smem_u32(const void* p) {
    uint32_t a;
    asm("{ .reg .u64 t; cvta.to.shared.u64 t, %1; cvt.u32.u64 %0, t; }" : "=r"(a) : "l"(p));
    return a;
}
__device__ __forceinline__ void cp16(uint32_t s, const void* g) {
    asm volatile("cp.async.cg.shared.global [%0], [%1], 16;" :: "r"(s), "l"(g));
}
__device__ __forceinline__ void cp_commit() {
    asm volatile("cp.async.commit_group;" ::: "memory");
}
__device__ __forceinline__ void cp_wait0() {
    asm volatile("cp.async.wait_group 0;" ::: "memory");
}
__device__ __forceinline__ void cp_wait1() {
    asm volatile("cp.async.wait_group 1;" ::: "memory");
}
__device__ __forceinline__ void ldsm4(uint32_t* r, uint32_t addr) {
    asm volatile("ldmatrix.sync.aligned.m8n8.x4.shared.b16 {%0,%1,%2,%3}, [%4];"
                 : "=r"(r[0]), "=r"(r[1]), "=r"(r[2]), "=r"(r[3]) : "r"(addr));
}
__device__ __forceinline__ void ldsm4t(uint32_t* r, uint32_t addr) {
    asm volatile("ldmatrix.sync.aligned.m8n8.x4.trans.shared.b16 {%0,%1,%2,%3}, [%4];"
                 : "=r"(r[0]), "=r"(r[1]), "=r"(r[2]), "=r"(r[3]) : "r"(addr));
}
__device__ __forceinline__ void mma_bf16(float* d, const uint32_t* a, const uint32_t* b) {
    asm volatile(
        "mma.sync.aligned.m16n8k16.row.col.f32.bf16.bf16.f32 "
        "{%0,%1,%2,%3}, {%4,%5,%6,%7}, {%8,%9}, {%0,%1,%2,%3};"
        : "+f"(d[0]), "+f"(d[1]), "+f"(d[2]), "+f"(d[3])
        : "r"(a[0]), "r"(a[1]), "r"(a[2]), "r"(a[3]), "r"(b[0]), "r"(b[1]));
}
__device__ __forceinline__ void mma_f16(float* d, uint32_t a0, uint32_t a1, uint32_t a2,
                                        uint32_t a3, uint32_t b0, uint32_t b1) {
    asm volatile(
        "mma.sync.aligned.m16n8k16.row.col.f32.f16.f16.f32 "
        "{%0,%1,%2,%3}, {%4,%5,%6,%7}, {%8,%9}, {%0,%1,%2,%3};"
        : "+f"(d[0]), "+f"(d[1]), "+f"(d[2]), "+f"(d[3])
        : "r"(a0), "r"(a1), "r"(a2), "r"(a3), "r"(b0), "r"(b1));
}
__device__ __forceinline__ float ex2f(float x) {
    float r;
    asm("ex2.approx.f32 %0, %1;" : "=f"(r) : "f"(x));
    return r;
}
__device__ __forceinline__ uint32_t packh2(float lo, float hi) {
    uint32_t r;
    asm("cvt.rn.f16x2.f32 %0, %1, %2;" : "=r"(r) : "f"(hi), "f"(lo));
    return r;
}
__device__ __forceinline__ uint32_t h2ex2(uint32_t x) {
    uint32_t r;
    asm("ex2.approx.f16x2 %0, %1;" : "=r"(r) : "r"(x));
    return r;
}

// =====================================================================
// Kernel 0a: split x (fp32) into bf16 hi + lo
// =====================================================================
__global__ void convert_x_kernel(const float* __restrict__ x)
{
    const int n4 = NROWS * HID / 4;
    for (int i = blockIdx.x * blockDim.x + threadIdx.x; i < n4; i += gridDim.x * blockDim.x) {
        float4 v = ((const float4*)x)[i];
        __nv_bfloat16 h0 = __float2bfloat16(v.x);
        __nv_bfloat16 h1 = __float2bfloat16(v.y);
        __nv_bfloat16 h2 = __float2bfloat16(v.z);
        __nv_bfloat16 h3 = __float2bfloat16(v.w);
        __nv_bfloat16 l0 = __float2bfloat16(v.x - __bfloat162float(h0));
        __nv_bfloat16 l1 = __float2bfloat16(v.y - __bfloat162float(h1));
        __nv_bfloat16 l2 = __float2bfloat16(v.z - __bfloat162float(h2));
        __nv_bfloat16 l3 = __float2bfloat16(v.w - __bfloat162float(h3));
        __nv_bfloat162 hp0 = __halves2bfloat162(h0, h1), hp1 = __halves2bfloat162(h2, h3);
        __nv_bfloat162 lp0 = __halves2bfloat162(l0, l1), lp1 = __halves2bfloat162(l2, l3);
        uint2 ho, lo;
        ho.x = *(uint32_t*)&hp0; ho.y = *(uint32_t*)&hp1;
        lo.x = *(uint32_t*)&lp0; lo.y = *(uint32_t*)&lp1;
        ((uint2*)g_xhi)[i] = ho;
        ((uint2*)g_xlo)[i] = lo;
    }
}

// =====================================================================
// Kernel 0b: transpose+split W  ->  wt[head][n][k] hi/lo bf16
// also resets the persistent-attention task counter each launch/replay
// =====================================================================
__global__ void convert_w_kernel(const float* __restrict__ Wq,
                                 const float* __restrict__ Wk,
                                 const float* __restrict__ Wv)
{
    if (blockIdx.x == 0 && threadIdx.x == 0) g_task = 0;
    const int per = HD * HID;                 // 262144
    const int tot = 3 * per;
    for (int i = blockIdx.x * blockDim.x + threadIdx.x; i < tot; i += gridDim.x * blockDim.x) {
        int head = i / per;
        int rem  = i - head * per;
        int n = rem / HID;
        int k = rem - n * HID;
        const float* W = (head == 0) ? Wq : (head == 1) ? Wk : Wv;
        float v = W[(size_t)k * HD + n];
        __nv_bfloat16 h = __float2bfloat16(v);
        __nv_bfloat16 l = __float2bfloat16(v - __bfloat162float(h));
        g_wthi[i] = h;
        g_wtlo[i] = l;
    }
}

// =====================================================================
// Kernel 1: mma.sync bf16-split projection.  BM=64 (grid 3 x 256),
// 256 threads, 8 warps (2x4): wm owns 32 rows, wn owns 32 cols.
// acc = 32 regs -> no spills under the 2-CTA/SM 128-reg budget.
// =====================================================================
#define PJ_BK     32
#define PJ_NCHUNK (HID / PJ_BK)       // 64
#define PJ_LDS    40                   // padded smem row stride (bf16 elems)
#define PJ_A_T    (64 * PJ_LDS * 2)    // 5120 B  (A tile: 64 rows)
#define PJ_B_T    (128 * PJ_LDS * 2)   // 10240 B (B tile: 128 rows)
#define PJ_OF_AH  0
#define PJ_OF_AL  (PJ_A_T)
#define PJ_OF_BH  (2 * PJ_A_T)
#define PJ_OF_BL  (2 * PJ_A_T + PJ_B_T)
#define PJ_BUF_B  (2 * PJ_A_T + 2 * PJ_B_T)   // 30720
#define PJ_SM_TOT (2 * PJ_BUF_B)               // 61440

__device__ __forceinline__ void split_store(__half* hi, __half* lo, size_t idx,
                                            float v0, float v1) {
    __half h0 = __float2half_rn(v0), h1 = __float2half_rn(v1);
    __half l0 = __float2half_rn(v0 - __half2float(h0));
    __half l1 = __float2half_rn(v1 - __half2float(h1));
    *(__half2*)(hi + idx) = __halves2half2(h0, h1);
    *(__half2*)(lo + idx) = __halves2half2(l0, l1);
}

__global__ __launch_bounds__(256, 2)
void proj_mma_kernel(const float* __restrict__ bq,
                     const float* __restrict__ bk,
                     const float* __restrict__ bv)
{
    extern __shared__ char smem[];
    const uint32_t sb = smem_u32(smem);

    const int t    = threadIdx.x;
    const int lane = t & 31;
    const int wid  = t >> 5;
    const int wm   = wid >> 2;       // 0..1  (32-row half)
    const int wn   = wid & 3;        // 0..3  (32-col quarter)
    const int head = blockIdx.x;
    const int m0   = blockIdx.y * 64;

    const __nv_bfloat16* xh = g_xhi;
    const __nv_bfloat16* xl = g_xlo;
    const __nv_bfloat16* wh = g_wthi + (size_t)head * HD * HID;
    const __nv_bfloat16* wl = g_wtlo + (size_t)head * HD * HID;

    // loaders: A tile 256 vecs -> 1/thread; B tile 512 vecs -> 2/thread
    const int arow = t >> 2;                 // 0..63
    const int brow0 = t >> 2;                // 0..63
    const int brow1 = 64 + (t >> 2);         // 64..127
    const int lkg  = (t & 3) * 8;            // 0,8,16,24

    float acc[2][4][4];
    #pragma unroll
    for (int i = 0; i < 2; ++i)
        #pragma unroll
        for (int j = 0; j < 4; ++j)
            #pragma unroll
            for (int u = 0; u < 4; ++u) acc[i][j][u] = 0.f;

    {
        const int kt = 0;
        const uint32_t bbase = sb;
        uint32_t soA = (uint32_t)(arow * PJ_LDS + lkg) * 2;
        cp16(bbase + PJ_OF_AH + soA, xh + (size_t)(m0 + arow) * HID + kt + lkg);
        cp16(bbase + PJ_OF_AL + soA, xl + (size_t)(m0 + arow) * HID + kt + lkg);
        uint32_t soB0 = (uint32_t)(brow0 * PJ_LDS + lkg) * 2;
        uint32_t soB1 = (uint32_t)(brow1 * PJ_LDS + lkg) * 2;
        cp16(bbase + PJ_OF_BH + soB0, wh + (size_t)brow0 * HID + kt + lkg);
        cp16(bbase + PJ_OF_BH + soB1, wh + (size_t)brow1 * HID + kt + lkg);
        cp16(bbase + PJ_OF_BL + soB0, wl + (size_t)brow0 * HID + kt + lkg);
        cp16(bbase + PJ_OF_BL + soB1, wl + (size_t)brow1 * HID + kt + lkg);
        cp_commit();
    }

    for (int c = 0; c < PJ_NCHUNK; ++c) {
        if (c + 1 < PJ_NCHUNK) {
            const int kt = (c + 1) * PJ_BK;
            const uint32_t bbase = sb + ((c + 1) & 1) * PJ_BUF_B;
            uint32_t soA = (uint32_t)(arow * PJ_LDS + lkg) * 2;
            cp16(bbase + PJ_OF_AH + soA, xh + (size_t)(m0 + arow) * HID + kt + lkg);
            cp16(bbase + PJ_OF_AL + soA, xl + (size_t)(m0 + arow) * HID + kt + lkg);
            uint32_t soB0 = (uint32_t)(brow0 * PJ_LDS + lkg) * 2;
            uint32_t soB1 = (uint32_t)(brow1 * PJ_LDS + lkg) * 2;
            cp16(bbase + PJ_OF_BH + soB0, wh + (size_t)brow0 * HID + kt + lkg);
            cp16(bbase + PJ_OF_BH + soB1, wh + (size_t)brow1 * HID + kt + lkg);
            cp16(bbase + PJ_OF_BL + soB0, wl + (size_t)brow0 * HID + kt + lkg);
            cp16(bbase + PJ_OF_BL + soB1, wl + (size_t)brow1 * HID + kt + lkg);
            cp_commit();
            cp_wait1();
        } else {
            cp_wait0();
        }
        __syncthreads();

        const uint32_t bbase = sb + (c & 1) * PJ_BUF_B;
        const uint32_t sAh = bbase + PJ_OF_AH;
        const uint32_t sAl = bbase + PJ_OF_AL;
        const uint32_t sBh = bbase + PJ_OF_BH;
        const uint32_t sBl = bbase + PJ_OF_BL;

        #pragma unroll
        for (int ks = 0; ks < 2; ++ks) {
            uint32_t bh[4][2], bl[4][2];
            #pragma unroll
            for (int g = 0; g < 2; ++g) {
                uint32_t off = (uint32_t)((wn * 32 + g * 16 + (lane & 15)) * PJ_LDS
                                          + ks * 16 + (lane >> 4) * 8) * 2;
                uint32_t r[4];
                ldsm4(r, sBh + off);
                bh[2 * g][0] = r[0]; bh[2 * g + 1][0] = r[1];
                bh[2 * g][1] = r[2]; bh[2 * g + 1][1] = r[3];
                ldsm4(r, sBl + off);
                bl[2 * g][0] = r[0]; bl[2 * g + 1][0] = r[1];
                bl[2 * g][1] = r[2]; bl[2 * g + 1][1] = r[3];
            }
            uint32_t ah[2][4], al[2][4];
            #pragma unroll
            for (int mt = 0; mt < 2; ++mt) {
                uint32_t off = (uint32_t)((wm * 32 + mt * 16 + (lane & 15)) * PJ_LDS
                                          + ks * 16 + (lane >> 4) * 8) * 2;
                ldsm4(ah[mt], sAh + off);
                ldsm4(al[mt], sAl + off);
            }
            // pass 1: hi*hi  (accumulator re-hit gap 8)
            #pragma unroll
            for (int mt = 0; mt < 2; ++mt)
                #pragma unroll
                for (int nt = 0; nt < 4; ++nt)
                    mma_bf16(acc[mt][nt], ah[mt], bh[nt]);
            // pass 2: hi*lo
            #pragma unroll
            for (int mt = 0; mt < 2; ++mt)
                #pragma unroll
                for (int nt = 0; nt < 4; ++nt)
                    mma_bf16(acc[mt][nt], ah[mt], bl[nt]);
            // pass 3: lo*hi
            #pragma unroll
            for (int mt = 0; mt < 2; ++mt)
                #pragma unroll
                for (int nt = 0; nt < 4; ++nt)
                    mma_bf16(acc[mt][nt], al[mt], bh[nt]);
        }
        __syncthreads();
    }

    // epilogue: bias (+log2e scale for Q) + fp16 split/plain store
    const float* bias = (head == 0) ? bq : (head == 1) ? bk : bv;
    const float scl = (head == 0) ? LOG2E : 1.0f;
    const int qrow = lane >> 2;
    const int qcol = (lane & 3) * 2;
    #pragma unroll
    for (int mt = 0; mt < 2; ++mt) {
        int row0 = m0 + wm * 32 + mt * 16 + qrow;
        #pragma unroll
        for (int nt = 0; nt < 4; ++nt) {
            int col = wn * 32 + nt * 8 + qcol;
            float b0 = __ldg(bias + col), b1 = __ldg(bias + col + 1);
            float v0 = (acc[mt][nt][0] + b0) * scl;
            float v1 = (acc[mt][nt][1] + b1) * scl;
            float v2 = (acc[mt][nt][2] + b0) * scl;
            float v3 = (acc[mt][nt][3] + b1) * scl;
            size_t i0 = (size_t)row0 * HD + col;
            size_t i1 = (size_t)(row0 + 8) * HD + col;
            if (head == 0) {
                split_store(g_qh, g_ql, i0, v0, v1);
                split_store(g_qh, g_ql, i1, v2, v3);
            } else if (head == 1) {
                split_store(g_kh, g_kl, i0, v0, v1);
                split_store(g_kh, g_kl, i1, v2, v3);
            } else {
                *(uint32_t*)(g_vv + i0) = packh2(v0, v1);
                *(uint32_t*)(g_vv + i1) = packh2(v2, v3);
            }
        }
    }
}

// =====================================================================
// Kernel 2: fp16 tensor-core causal flash attention.
// Persistent CTAs (296), 128 threads (4 warps), atomic task queue,
// heavy-first.  BM=64, BN=64, D=128.  Q in registers, K/V dbl-buffered.
// PINGPONG: the 64-col tile is processed as two 32-col halves with
// issue order QK(h0), QK(h1), prefetch, SM(h0), PV(h0), SM(h1), PV(h1)
// so softmax ALU/MUFU overlaps tensor-pipe drain of the other half.
// m initialized to -1e4 (finite) so an all-masked half yields p=0.
// =====================================================================
#define QSTRB 272    // 136 fp16 elems * 2B  (K and Q tiles)
#define VSTRB 304    // 152 fp16 elems * 2B  (V tile, +ones col at 128)
#define ST_B  54272  // one K/V stage: KH + KL + V
#define ST_KH 0
#define ST_KL 17408
#define ST_V  34816
#define SM_TASK 108544
#define SM_ATT_TOT 108560
#define N_TASKS 256

__global__ __launch_bounds__(128)
void attn_kernel(float* __restrict__ outp)
{
    extern __shared__ char smem[];
    const uint32_t sb = smem_u32(smem);
    const int t = threadIdx.x;
    const int l = t & 31;
    const int w = t >> 5;

    // init V pad columns for BOTH stages (col 128 = ones, 129..143 = 0)
    #pragma unroll
    for (int s2 = 0; s2 < 2; ++s2)
        for (int i = t; i < 64 * 16; i += 128) {
            int row = i >> 4;
            int c   = 128 + (i & 15);
            ((__half*)(smem + s2 * ST_B + ST_V))[row * 152 + c] =
                (c == 128) ? __float2half(1.0f) : __float2half(0.0f);
        }

    // ldsm address components (constant per thread)
    const uint32_t qa_off = (uint32_t)(w * 16 + (l & 15)) * QSTRB + ((l >> 4) * 8) * 2;
    const uint32_t kb_row = (uint32_t)((l >> 4) * 8 + (l & 7)) * QSTRB;
    const uint32_t kb_col = (uint32_t)(((l >> 3) & 1) * 8) * 2;
    const uint32_t vb_row = (uint32_t)(((l >> 3) & 1) * 8 + (l & 7)) * VSTRB;
    const uint32_t vb_col = (uint32_t)((l >> 4) * 8) * 2;

    const float cf = 0.0883883476483184406f;   // 1/sqrt(128)

    while (true) {
        __syncthreads();
        if (t == 0) *(int*)(smem + SM_TASK) = atomicAdd(&g_task, 1);
        __syncthreads();
        const int task = *(int*)(smem + SM_TASK);
        if (task >= N_TASKS) break;

        const int qb = 63 - (task >> 2);
        const int b  = task & 3;
        const int q0 = qb * 64;

        const __half* qh = g_qh + (size_t)b * S_LEN * HD;
        const __half* ql = g_ql + (size_t)b * S_LEN * HD;
        const __half* kh = g_kh + (size_t)b * S_LEN * HD;
        const __half* kl = g_kl + (size_t)b * S_LEN * HD;
        const __half* vv = g_vv + (size_t)b * S_LEN * HD;

        // ---- stage Q through stage0 KH/KL, then ldsm into registers ----
        #pragma unroll
        for (int p = 0; p < 8; ++p) {
            int vec = t + 128 * p;
            int row = vec >> 4;
            int cv  = vec & 15;
            uint32_t so = (uint32_t)row * QSTRB + cv * 16;
            const size_t g = (size_t)(q0 + row) * HD + cv * 8;
            cp16(sb + ST_KH + so, qh + g);
            cp16(sb + ST_KL + so, ql + g);
        }
        cp_commit();
        cp_wait0();
        __syncthreads();

        uint32_t qah[8][4], qal[8][4];
        #pragma unroll
        for (int ks = 0; ks < 8; ++ks) {
            ldsm4(qah[ks], sb + ST_KH + qa_off + ks * 32);
            ldsm4(qal[ks], sb + ST_KL + qa_off + ks * 32);
        }
        __syncthreads();

        // ---- prologue: load K/V stage 0 ----
        #pragma unroll
        for (int p = 0; p < 8; ++p) {
            int vec = t + 128 * p;
            int row = vec >> 4;
            int cv  = vec & 15;
            const size_t g = (size_t)row * HD + cv * 8;
            cp16(sb + ST_KH + (uint32_t)row * QSTRB + cv * 16, kh + g);
            cp16(sb + ST_KL + (uint32_t)row * QSTRB + cv * 16, kl + g);
            cp16(sb + ST_V  + (uint32_t)row * VSTRB + cv * 16, vv + g);
        }
        cp_commit();

        float o[18][4];
        #pragma unroll
        for (int i = 0; i < 18; ++i)
            #pragma unroll
            for (int u = 0; u < 4; ++u) o[i][u] = 0.f;
        float mA = -1e4f, mB = -1e4f;

        const int rA = w * 16 + (l >> 2);
        const int rB = rA + 8;

        for (int kb = 0; kb <= qb; ++kb) {
            cp_wait0();
            __syncthreads();

            const uint32_t cb = sb + (uint32_t)(kb & 1) * ST_B;
            const bool diag = (kb == qb);

            float s[8][4];
            #pragma unroll
            for (int n = 0; n < 8; ++n)
                #pragma unroll
                for (int u = 0; u < 4; ++u) s[n][u] = 0.f;

            // ---- QK half h: cols h*32..h*32+31  (u = 2h, 2h+1) ----
            #pragma unroll
            for (int h = 0; h < 2; ++h) {
                #pragma unroll
                for (int ks = 0; ks < 8; ++ks) {
                    uint32_t bh[2][4], bl[2][4];
                    #pragma unroll
                    for (int uu = 0; uu < 2; ++uu) {
                        int u = 2 * h + uu;
                        uint32_t off = (uint32_t)(u * 16) * QSTRB + kb_row + ks * 32 + kb_col;
                        ldsm4(bh[uu], cb + ST_KH + off);
                        ldsm4(bl[uu], cb + ST_KL + off);
                    }
                    #pragma unroll
                    for (int uu = 0; uu < 2; ++uu) {
                        int n0 = 4 * h + 2 * uu;
                        mma_f16(s[n0],     qah[ks][0], qah[ks][1], qah[ks][2], qah[ks][3], bh[uu][0], bh[uu][1]);
                        mma_f16(s[n0 + 1], qah[ks][0], qah[ks][1], qah[ks][2], qah[ks][3], bh[uu][2], bh[uu][3]);
                    }
                    #pragma unroll
                    for (int uu = 0; uu < 2; ++uu) {
                        int n0 = 4 * h + 2 * uu;
                        mma_f16(s[n0],     qah[ks][0], qah[ks][1], qah[ks][2], qah[ks][3], bl[uu][0], bl[uu][1]);
                        mma_f16(s[n0 + 1], qah[ks][0], qah[ks][1], qah[ks][2], qah[ks][3], bl[uu][2], bl[uu][3]);
                    }
                    #pragma unroll
                    for (int uu = 0; uu < 2; ++uu) {
                        int n0 = 4 * h + 2 * uu;
                        mma_f16(s[n0],     qal[ks][0], qal[ks][1], qal[ks][2], qal[ks][3], bh[uu][0], bh[uu][1]);
                        mma_f16(s[n0 + 1], qal[ks][0], qal[ks][1], qal[ks][2], qal[ks][3], bh[uu][2], bh[uu][3]);
                    }
                }
            }

            // ---- issue prefetch of next stage ----
            if (kb + 1 <= qb) {
                const uint32_t nb = sb + (uint32_t)((kb + 1) & 1) * ST_B;
                #pragma unroll
                for (int p = 0; p < 8; ++p) {
                    int vec = t + 128 * p;
                    int row = vec >> 4;
                    int cv  = vec & 15;
                    const size_t g = (size_t)((kb + 1) * 64 + row) * HD + cv * 8;
                    cp16(nb + ST_KH + (uint32_t)row * QSTRB + cv * 16, kh + g);
                    cp16(nb + ST_KL + (uint32_t)row * QSTRB + cv * 16, kl + g);
                    cp16(nb + ST_V  + (uint32_t)row * VSTRB + cv * 16, vv + g);
                }
                cp_commit();
            }

            // ---- per-half: softmax then PV (tensor overlaps other half) ----
            #pragma unroll
            for (int h = 0; h < 2; ++h) {
                // mask (diag block only)
                if (diag) {
                    #pragma unroll
                    for (int nn = 0; nn < 4; ++nn) {
                        int n = 4 * h + nn;
                        int c0 = n * 8 + 2 * (l & 3);
                        if (c0     > rA) s[n][0] = -1e30f;
                        if (c0 + 1 > rA) s[n][1] = -1e30f;
                        if (c0     > rB) s[n][2] = -1e30f;
                        if (c0 + 1 > rB) s[n][3] = -1e30f;
                    }
                }
                float mxA = s[4 * h][0], mxB = s[4 * h][2];
                #pragma unroll
                for (int nn = 0; nn < 4; ++nn) {
                    int n = 4 * h + nn;
                    mxA = fmaxf(mxA, fmaxf(s[n][0], s[n][1]));
                    mxB = fmaxf(mxB, fmaxf(s[n][2], s[n][3]));
                }
                mxA = fmaxf(mxA, __shfl_xor_sync(0xffffffffu, mxA, 1));
                mxA = fmaxf(mxA, __shfl_xor_sync(0xffffffffu, mxA, 2));
                mxB = fmaxf(mxB, __shfl_xor_sync(0xffffffffu, mxB, 1));
                mxB = fmaxf(mxB, __shfl_xor_sync(0xffffffffu, mxB, 2));
                const float nmA = fmaxf(mA, mxA);
                const float nmB = fmaxf(mB, mxB);

                uint32_t pA[4], pB[4];
                #pragma unroll
                for (int nn = 0; nn < 4; ++nn) {
                    int n = 4 * h + nn;
                    pA[nn] = h2ex2(packh2(s[n][0] - nmA, s[n][1] - nmA));
                    pB[nn] = h2ex2(packh2(s[n][2] - nmB, s[n][3] - nmB));
                }

                if (nmA > mA) {
                    float aA = ex2f(mA - nmA);
                    #pragma unroll
                    for (int i = 0; i < 17; ++i) { o[i][0] *= aA; o[i][1] *= aA; }
                    mA = nmA;
                }
                if (nmB > mB) {
                    float aB = ex2f(mB - nmB);
                    #pragma unroll
                    for (int i = 0; i < 17; ++i) { o[i][2] *= aB; o[i][3] *= aB; }
                    mB = nmB;
                }

                // PV for this half: kt = 2h, 2h+1
                #pragma unroll
                for (int kk = 0; kk < 2; ++kk) {
                    int kt = 2 * h + kk;
                    uint32_t a0 = pA[2 * kk], a1 = pB[2 * kk];
                    uint32_t a2 = pA[2 * kk + 1], a3 = pB[2 * kk + 1];
                    uint32_t vb[9][4];
                    #pragma unroll
                    for (int u = 0; u < 9; ++u) {
                        uint32_t off = (uint32_t)(kt * 16) * VSTRB + vb_row + u * 32 + vb_col;
                        ldsm4t(vb[u], cb + ST_V + off);
                    }
                    #pragma unroll
                    for (int u = 0; u < 9; ++u) {
                        mma_f16(o[2 * u],     a0, a1, a2, a3, vb[u][0], vb[u][1]);
                        mma_f16(o[2 * u + 1], a0, a1, a2, a3, vb[u][2], vb[u][3]);
                    }
                }
            }
            __syncthreads();
        }

        // ---- epilogue ----
        const float lA = __shfl_sync(0xffffffffu, o[16][0], (l >> 2) << 2);
        const float lB = __shfl_sync(0xffffffffu, o[16][2], (l >> 2) << 2);
        const float sA = cf / lA;
        const float sB = cf / lB;
        const int gA = q0 + rA;
        const int gB = q0 + rB;
        float* op = outp + (size_t)b * S_LEN * HD;
        #pragma unroll
        for (int n = 0; n < 16; ++n) {
            int c = n * 8 + 2 * (l & 3);
            float2 vA, vB;
            vA.x = o[n][0] * sA; vA.y = o[n][1] * sA;
            vB.x = o[n][2] * sB; vB.y = o[n][3] * sB;
            *(float2*)(op + (size_t)gA * HD + c) = vA;
            *(float2*)(op + (size_t)gB * HD + c) = vB;
        }
    }
}

// =====================================================================
extern "C" void kernel_launch(void* const* d_in, const int* in_sizes, int n_in,
                              void* d_out, int out_size)
{
    const float* x  = (const float*)d_in[0];
    const float* Wq = (const float*)d_in[1];
    const float* bq = (const float*)d_in[2];
    const float* Wk = (const float*)d_in[3];
    const float* bk = (const float*)d_in[4];
    const float* Wv = (const float*)d_in[5];
    const float* bv = (const float*)d_in[6];
    float* out = (float*)d_out;

    convert_x_kernel<<<8192, 256>>>(x);
    convert_w_kernel<<<1024, 256>>>(Wq, Wk, Wv);

    cudaFuncSetAttribute(proj_mma_kernel,
                         cudaFuncAttributeMaxDynamicSharedMemorySize, PJ_SM_TOT);
    dim3 pg(3, 256);
    proj_mma_kernel<<<pg, 256, PJ_SM_TOT>>>(bq, bk, bv);

    cudaFuncSetAttribute(attn_kernel,
                         cudaFuncAttributeMaxDynamicSharedMemorySize, SM_ATT_TOT);
    attn_kernel<<<296, 128, SM_ATT_TOT>>>(out);
}

// round 10
// speedup vs baseline: 1.1582x; 1.1582x over previous
#include <cuda_runtime.h>
#include <cuda_bf16.h>
#include <cuda_fp16.h>
#include <math.h>
#include <stdint.h>

#define NB    4
#define S_LEN 4096
#define HID   2048
#define HD    128
#define NROWS (NB * S_LEN)          // 16384
#define LOG2E 1.4426950408889634f

// Split-KV chunking: chunk = 8 KV blocks.  nch(qb) = (qb>>3)+1.
// total tasks = 4 * sum_{qb} nch = 1152.
#define CHUNK    8
#define N_TASKS  1152

// ---------------- scratch (no allocs allowed) ----------------
__device__ __nv_bfloat16 g_xhi[NROWS * HID];
__device__ __nv_bfloat16 g_xlo[NROWS * HID];
__device__ __nv_bfloat16 g_wthi[3 * HD * HID];   // [head][n][k] = W^T split hi
__device__ __nv_bfloat16 g_wtlo[3 * HD * HID];
__device__ __half g_qh[NROWS * HD];   // Q*log2e hi/lo fp16
__device__ __half g_ql[NROWS * HD];
__device__ __half g_kh[NROWS * HD];
__device__ __half g_kl[NROWS * HD];
__device__ __half g_vv[NROWS * HD];   // V fp16
__device__ float g_po[N_TASKS][64][HD];   // unnormalized partial O
__device__ float g_pml[N_TASKS][64][2];   // per-row {m, l}
__device__ int g_task;

// ======================= helpers =======================
__device__ __forceinline__ uint32_t smem_u32(const void* p) {
    uint32_t a;
    asm("{ .reg .u64 t; cvta.to.shared.u64 t, %1; cvt.u32.u64 %0, t; }" : "=r"(a) : "l"(p));
    return a;
}
__device__ __forceinline__ void cp16(uint32_t s, const void* g) {
    asm volatile("cp.async.cg.shared.global [%0], [%1], 16;" :: "r"(s), "l"(g));
}
__device__ __forceinline__ void cp_commit() {
    asm volatile("cp.async.commit_group;" ::: "memory");
}
__device__ __forceinline__ void cp_wait0() {
    asm volatile("cp.async.wait_group 0;" ::: "memory");
}
__device__ __forceinline__ void cp_wait1() {
    asm volatile("cp.async.wait_group 1;" ::: "memory");
}
__device__ __forceinline__ void ldsm4(uint32_t* r, uint32_t addr) {
    asm volatile("ldmatrix.sync.aligned.m8n8.x4.shared.b16 {%0,%1,%2,%3}, [%4];"
                 : "=r"(r[0]), "=r"(r[1]), "=r"(r[2]), "=r"(r[3]) : "r"(addr));
}
__device__ __forceinline__ void ldsm4t(uint32_t* r, uint32_t addr) {
    asm volatile("ldmatrix.sync.aligned.m8n8.x4.trans.shared.b16 {%0,%1,%2,%3}, [%4];"
                 : "=r"(r[0]), "=r"(r[1]), "=r"(r[2]), "=r"(r[3]) : "r"(addr));
}
__device__ __forceinline__ void mma_bf16(float* d, const uint32_t* a, const uint32_t* b) {
    asm volatile(
        "mma.sync.aligned.m16n8k16.row.col.f32.bf16.bf16.f32 "
        "{%0,%1,%2,%3}, {%4,%5,%6,%7}, {%8,%9}, {%0,%1,%2,%3};"
        : "+f"(d[0]), "+f"(d[1]), "+f"(d[2]), "+f"(d[3])
        : "r"(a[0]), "r"(a[1]), "r"(a[2]), "r"(a[3]), "r"(b[0]), "r"(b[1]));
}
__device__ __forceinline__ void mma_f16(float* d, uint32_t a0, uint32_t a1, uint32_t a2,
                                        uint32_t a3, uint32_t b0, uint32_t b1) {
    asm volatile(
        "mma.sync.aligned.m16n8k16.row.col.f32.f16.f16.f32 "
        "{%0,%1,%2,%3}, {%4,%5,%6,%7}, {%8,%9}, {%0,%1,%2,%3};"
        : "+f"(d[0]), "+f"(d[1]), "+f"(d[2]), "+f"(d[3])
        : "r"(a0), "r"(a1), "r"(a2), "r"(a3), "r"(b0), "r"(b1));
}
__device__ __forceinline__ float ex2f(float x) {
    float r;
    asm("ex2.approx.f32 %0, %1;" : "=f"(r) : "f"(x));
    return r;
}
__device__ __forceinline__ uint32_t packh2(float lo, float hi) {
    uint32_t r;
    asm("cvt.rn.f16x2.f32 %0, %1, %2;" : "=r"(r) : "f"(hi), "f"(lo));
    return r;
}
__device__ __forceinline__ uint32_t h2ex2(uint32_t x) {
    uint32_t r;
    asm("ex2.approx.f16x2 %0, %1;" : "=r"(r) : "r"(x));
    return r;
}

// =====================================================================
// Kernel 0a: split x (fp32) into bf16 hi + lo
// =====================================================================
__global__ void convert_x_kernel(const float* __restrict__ x)
{
    const int n4 = NROWS * HID / 4;
    for (int i = blockIdx.x * blockDim.x + threadIdx.x; i < n4; i += gridDim.x * blockDim.x) {
        float4 v = ((const float4*)x)[i];
        __nv_bfloat16 h0 = __float2bfloat16(v.x);
        __nv_bfloat16 h1 = __float2bfloat16(v.y);
        __nv_bfloat16 h2 = __float2bfloat16(v.z);
        __nv_bfloat16 h3 = __float2bfloat16(v.w);
        __nv_bfloat16 l0 = __float2bfloat16(v.x - __bfloat162float(h0));
        __nv_bfloat16 l1 = __float2bfloat16(v.y - __bfloat162float(h1));
        __nv_bfloat16 l2 = __float2bfloat16(v.z - __bfloat162float(h2));
        __nv_bfloat16 l3 = __float2bfloat16(v.w - __bfloat162float(h3));
        __nv_bfloat162 hp0 = __halves2bfloat162(h0, h1), hp1 = __halves2bfloat162(h2, h3);
        __nv_bfloat162 lp0 = __halves2bfloat162(l0, l1), lp1 = __halves2bfloat162(l2, l3);
        uint2 ho, lo;
        ho.x = *(uint32_t*)&hp0; ho.y = *(uint32_t*)&hp1;
        lo.x = *(uint32_t*)&lp0; lo.y = *(uint32_t*)&lp1;
        ((uint2*)g_xhi)[i] = ho;
        ((uint2*)g_xlo)[i] = lo;
    }
}

// =====================================================================
// Kernel 0b: transpose+split W  ->  wt[head][n][k] hi/lo bf16
// also resets the persistent-attention task counter each launch/replay
// =====================================================================
__global__ void convert_w_kernel(const float* __restrict__ Wq,
                                 const float* __restrict__ Wk,
                                 const float* __restrict__ Wv)
{
    if (blockIdx.x == 0 && threadIdx.x == 0) g_task = 0;
    const int per = HD * HID;                 // 262144
    const int tot = 3 * per;
    for (int i = blockIdx.x * blockDim.x + threadIdx.x; i < tot; i += gridDim.x * blockDim.x) {
        int head = i / per;
        int rem  = i - head * per;
        int n = rem / HID;
        int k = rem - n * HID;
        const float* W = (head == 0) ? Wq : (head == 1) ? Wk : Wv;
        float v = W[(size_t)k * HD + n];
        __nv_bfloat16 h = __float2bfloat16(v);
        __nv_bfloat16 l = __float2bfloat16(v - __bfloat162float(h));
        g_wthi[i] = h;
        g_wtlo[i] = l;
    }
}

// =====================================================================
// Kernel 1: mma.sync bf16-split projection (round-8 version).
// grid(3,128): head x 128-row tile, 256 threads (2x4 warps, 64x32 each).
// =====================================================================
#define PJ_BK     32
#define PJ_NCHUNK (HID / PJ_BK)     // 64
#define PJ_LDS    40                 // padded smem row stride (bf16 elems)
#define PJ_TILE_B (128 * PJ_LDS * 2) // 10240 bytes per tile
#define PJ_BUF_B  (4 * PJ_TILE_B)    // Ah, Al, Bh, Bl
#define PJ_SM_TOT (2 * PJ_BUF_B)     // double buffered: 81920 bytes

__device__ __forceinline__ void split_store(__half* hi, __half* lo, size_t idx,
                                            float v0, float v1) {
    __half h0 = __float2half_rn(v0), h1 = __float2half_rn(v1);
    __half l0 = __float2half_rn(v0 - __half2float(h0));
    __half l1 = __float2half_rn(v1 - __half2float(h1));
    *(__half2*)(hi + idx) = __halves2half2(h0, h1);
    *(__half2*)(lo + idx) = __halves2half2(l0, l1);
}

__global__ __launch_bounds__(256, 2)
void proj_mma_kernel(const float* __restrict__ bq,
                     const float* __restrict__ bk,
                     const float* __restrict__ bv)
{
    extern __shared__ char smem[];
    const uint32_t sb = smem_u32(smem);

    const int t    = threadIdx.x;
    const int lane = t & 31;
    const int wid  = t >> 5;
    const int wm   = wid >> 2;       // 0..1  (64-row half)
    const int wn   = wid & 3;        // 0..3  (32-col quarter)
    const int head = blockIdx.x;
    const int m0   = blockIdx.y * 128;

    const __nv_bfloat16* xh = g_xhi;
    const __nv_bfloat16* xl = g_xlo;
    const __nv_bfloat16* wh = g_wthi + (size_t)head * HD * HID;
    const __nv_bfloat16* wl = g_wtlo + (size_t)head * HD * HID;

    const int lrow0 = (t + 0)   >> 2;            // 0..63
    const int lrow1 = (t + 256) >> 2;            // 64..127
    const int lkg   = (t & 3) * 8;               // 0,8,16,24

    float acc[4][4][4];
    #pragma unroll
    for (int i = 0; i < 4; ++i)
        #pragma unroll
        for (int j = 0; j < 4; ++j)
            #pragma unroll
            for (int u = 0; u < 4; ++u) acc[i][j][u] = 0.f;

    {
        const int kt = 0;
        const uint32_t bbase = sb;
        #pragma unroll
        for (int p = 0; p < 2; ++p) {
            int row = p ? lrow1 : lrow0;
            uint32_t so = (uint32_t)(row * PJ_LDS + lkg) * 2;
            cp16(bbase + 0 * PJ_TILE_B + so, xh + (size_t)(m0 + row) * HID + kt + lkg);
            cp16(bbase + 1 * PJ_TILE_B + so, xl + (size_t)(m0 + row) * HID + kt + lkg);
            cp16(bbase + 2 * PJ_TILE_B + so, wh + (size_t)row * HID + kt + lkg);
            cp16(bbase + 3 * PJ_TILE_B + so, wl + (size_t)row * HID + kt + lkg);
        }
        cp_commit();
    }

    for (int c = 0; c < PJ_NCHUNK; ++c) {
        if (c + 1 < PJ_NCHUNK) {
            const int kt = (c + 1) * PJ_BK;
            const uint32_t bbase = sb + ((c + 1) & 1) * PJ_BUF_B;
            #pragma unroll
            for (int p = 0; p < 2; ++p) {
                int row = p ? lrow1 : lrow0;
                uint32_t so = (uint32_t)(row * PJ_LDS + lkg) * 2;
                cp16(bbase + 0 * PJ_TILE_B + so, xh + (size_t)(m0 + row) * HID + kt + lkg);
                cp16(bbase + 1 * PJ_TILE_B + so, xl + (size_t)(m0 + row) * HID + kt + lkg);
                cp16(bbase + 2 * PJ_TILE_B + so, wh + (size_t)row * HID + kt + lkg);
                cp16(bbase + 3 * PJ_TILE_B + so, wl + (size_t)row * HID + kt + lkg);
            }
            cp_commit();
            cp_wait1();
        } else {
            cp_wait0();
        }
        __syncthreads();

        const uint32_t bbase = sb + (c & 1) * PJ_BUF_B;
        const uint32_t sAh = bbase + 0 * PJ_TILE_B;
        const uint32_t sAl = bbase + 1 * PJ_TILE_B;
        const uint32_t sBh = bbase + 2 * PJ_TILE_B;
        const uint32_t sBl = bbase + 3 * PJ_TILE_B;

        #pragma unroll
        for (int ks = 0; ks < 2; ++ks) {
            uint32_t bh[4][2], bl[4][2];
            #pragma unroll
            for (int g = 0; g < 2; ++g) {
                uint32_t off = (uint32_t)((wn * 32 + g * 16 + (lane & 15)) * PJ_LDS
                                          + ks * 16 + (lane >> 4) * 8) * 2;
                uint32_t r[4];
                ldsm4(r, sBh + off);
                bh[2 * g][0] = r[0]; bh[2 * g + 1][0] = r[1];
                bh[2 * g][1] = r[2]; bh[2 * g + 1][1] = r[3];
                ldsm4(r, sBl + off);
                bl[2 * g][0] = r[0]; bl[2 * g + 1][0] = r[1];
                bl[2 * g][1] = r[2]; bl[2 * g + 1][1] = r[3];
            }
            #pragma unroll
            for (int mp = 0; mp < 2; ++mp) {
                uint32_t ah[2][4], al[2][4];
                #pragma unroll
                for (int q2 = 0; q2 < 2; ++q2) {
                    int mt = mp * 2 + q2;
                    uint32_t off = (uint32_t)((wm * 64 + mt * 16 + (lane & 15)) * PJ_LDS
                                              + ks * 16 + (lane >> 4) * 8) * 2;
                    ldsm4(ah[q2], sAh + off);
                    ldsm4(al[q2], sAl + off);
                }
                #pragma unroll
                for (int q2 = 0; q2 < 2; ++q2)
                    #pragma unroll
                    for (int nt = 0; nt < 4; ++nt)
                        mma_bf16(acc[mp * 2 + q2][nt], ah[q2], bh[nt]);
                #pragma unroll
                for (int q2 = 0; q2 < 2; ++q2)
                    #pragma unroll
                    for (int nt = 0; nt < 4; ++nt)
                        mma_bf16(acc[mp * 2 + q2][nt], ah[q2], bl[nt]);
                #pragma unroll
                for (int q2 = 0; q2 < 2; ++q2)
                    #pragma unroll
                    for (int nt = 0; nt < 4; ++nt)
                        mma_bf16(acc[mp * 2 + q2][nt], al[q2], bh[nt]);
            }
        }
        __syncthreads();
    }

    // epilogue: bias (+log2e scale for Q) + fp16 split/plain store
    const float* bias = (head == 0) ? bq : (head == 1) ? bk : bv;
    const float scl = (head == 0) ? LOG2E : 1.0f;
    const int qrow = lane >> 2;
    const int qcol = (lane & 3) * 2;
    #pragma unroll
    for (int mt = 0; mt < 4; ++mt) {
        int row0 = m0 + wm * 64 + mt * 16 + qrow;
        #pragma unroll
        for (int nt = 0; nt < 4; ++nt) {
            int col = wn * 32 + nt * 8 + qcol;
            float b0 = __ldg(bias + col), b1 = __ldg(bias + col + 1);
            float v0 = (acc[mt][nt][0] + b0) * scl;
            float v1 = (acc[mt][nt][1] + b1) * scl;
            float v2 = (acc[mt][nt][2] + b0) * scl;
            float v3 = (acc[mt][nt][3] + b1) * scl;
            size_t i0 = (size_t)row0 * HD + col;
            size_t i1 = (size_t)(row0 + 8) * HD + col;
            if (head == 0) {
                split_store(g_qh, g_ql, i0, v0, v1);
                split_store(g_qh, g_ql, i1, v2, v3);
            } else if (head == 1) {
                split_store(g_kh, g_kl, i0, v0, v1);
                split_store(g_kh, g_kl, i1, v2, v3);
            } else {
                *(uint32_t*)(g_vv + i0) = packh2(v0, v1);
                *(uint32_t*)(g_vv + i1) = packh2(v2, v3);
            }
        }
    }
}

// =====================================================================
// Kernel 2: fp16 tensor-core causal flash attention, SPLIT-KV.
// Persistent CTAs (296), 128 threads.  Task = (b, qb, kv-chunk of 8
// blocks); 1152 near-uniform tasks -> balanced makespan.  Each task
// writes an unnormalized partial (O, m, l) to its slot; merge_kernel
// combines.  Q in regs, K/V double-buffered (round-8 inner loop).
// =====================================================================
#define QSTRB 272    // 136 fp16 elems * 2B  (K and Q tiles)
#define VSTRB 304    // 152 fp16 elems * 2B  (V tile, +ones col at 128)
#define ST_B  54272  // one K/V stage: KH + KL + V
#define ST_KH 0
#define ST_KL 17408
#define ST_V  34816
#define SM_TASK 108544
#define SM_ATT_TOT 108560

__global__ __launch_bounds__(128)
void attn_kernel()
{
    extern __shared__ char smem[];
    const uint32_t sb = smem_u32(smem);
    const int t = threadIdx.x;
    const int l = t & 31;
    const int w = t >> 5;

    // init V pad columns for BOTH stages (col 128 = ones, 129..143 = 0)
    #pragma unroll
    for (int s2 = 0; s2 < 2; ++s2)
        for (int i = t; i < 64 * 16; i += 128) {
            int row = i >> 4;
            int c   = 128 + (i & 15);
            ((__half*)(smem + s2 * ST_B + ST_V))[row * 152 + c] =
                (c == 128) ? __float2half(1.0f) : __float2half(0.0f);
        }

    const uint32_t qa_off = (uint32_t)(w * 16 + (l & 15)) * QSTRB + ((l >> 4) * 8) * 2;
    const uint32_t kb_row = (uint32_t)((l >> 4) * 8 + (l & 7)) * QSTRB;
    const uint32_t kb_col = (uint32_t)(((l >> 3) & 1) * 8) * 2;
    const uint32_t vb_row = (uint32_t)(((l >> 3) & 1) * 8 + (l & 7)) * VSTRB;
    const uint32_t vb_col = (uint32_t)((l >> 4) * 8) * 2;

    while (true) {
        __syncthreads();
        if (t == 0) *(int*)(smem + SM_TASK) = atomicAdd(&g_task, 1);
        __syncthreads();
        const int task = *(int*)(smem + SM_TASK);
        if (task >= N_TASKS) break;

        // decode task -> (qb desc, chunk, batch)
        int id = task, qb = 63, ch, b;
        for (;;) {
            int cnt = 4 * ((qb >> 3) + 1);
            if (id < cnt) { ch = id >> 2; b = id & 3; break; }
            id -= cnt; --qb;
        }
        const int q0  = qb * 64;
        const int kv0 = ch * CHUNK;
        const int kv1 = min(kv0 + CHUNK, qb + 1);

        const __half* qh = g_qh + (size_t)b * S_LEN * HD;
        const __half* ql = g_ql + (size_t)b * S_LEN * HD;
        const __half* kh = g_kh + (size_t)b * S_LEN * HD;
        const __half* kl = g_kl + (size_t)b * S_LEN * HD;
        const __half* vv = g_vv + (size_t)b * S_LEN * HD;

        // ---- stage Q through stage0 KH/KL, then ldsm into registers ----
        #pragma unroll
        for (int p = 0; p < 8; ++p) {
            int vec = t + 128 * p;
            int row = vec >> 4;
            int cv  = vec & 15;
            uint32_t so = (uint32_t)row * QSTRB + cv * 16;
            const size_t g = (size_t)(q0 + row) * HD + cv * 8;
            cp16(sb + ST_KH + so, qh + g);
            cp16(sb + ST_KL + so, ql + g);
        }
        cp_commit();
        cp_wait0();
        __syncthreads();

        uint32_t qah[8][4], qal[8][4];
        #pragma unroll
        for (int ks = 0; ks < 8; ++ks) {
            ldsm4(qah[ks], sb + ST_KH + qa_off + ks * 32);
            ldsm4(qal[ks], sb + ST_KL + qa_off + ks * 32);
        }
        __syncthreads();

        // ---- prologue: load K/V stage for kb = kv0 ----
        #pragma unroll
        for (int p = 0; p < 8; ++p) {
            int vec = t + 128 * p;
            int row = vec >> 4;
            int cv  = vec & 15;
            const size_t g = (size_t)(kv0 * 64 + row) * HD + cv * 8;
            cp16(sb + (uint32_t)(kv0 & 1) * ST_B + ST_KH + (uint32_t)row * QSTRB + cv * 16, kh + g);
            cp16(sb + (uint32_t)(kv0 & 1) * ST_B + ST_KL + (uint32_t)row * QSTRB + cv * 16, kl + g);
            cp16(sb + (uint32_t)(kv0 & 1) * ST_B + ST_V  + (uint32_t)row * VSTRB + cv * 16, vv + g);
        }
        cp_commit();

        float o[18][4];
        #pragma unroll
        for (int i = 0; i < 18; ++i)
            #pragma unroll
            for (int u = 0; u < 4; ++u) o[i][u] = 0.f;
        float mA = -1e4f, mB = -1e4f;

        const int rA = w * 16 + (l >> 2);
        const int rB = rA + 8;

        for (int kb = kv0; kb < kv1; ++kb) {
            cp_wait0();
            __syncthreads();

            const uint32_t cb = sb + (uint32_t)(kb & 1) * ST_B;

            // ---- S = Q K^T: batched ldsm per ks, split-pass ordering ----
            float s[8][4];
            #pragma unroll
            for (int n = 0; n < 8; ++n)
                #pragma unroll
                for (int u = 0; u < 4; ++u) s[n][u] = 0.f;

            #pragma unroll
            for (int ks = 0; ks < 8; ++ks) {
                uint32_t bh[4][4], bl[4][4];
                #pragma unroll
                for (int u = 0; u < 4; ++u) {
                    uint32_t off = (uint32_t)(u * 16) * QSTRB + kb_row + ks * 32 + kb_col;
                    ldsm4(bh[u], cb + ST_KH + off);
                    ldsm4(bl[u], cb + ST_KL + off);
                }
                #pragma unroll
                for (int u = 0; u < 4; ++u) {
                    mma_f16(s[2 * u],     qah[ks][0], qah[ks][1], qah[ks][2], qah[ks][3], bh[u][0], bh[u][1]);
                    mma_f16(s[2 * u + 1], qah[ks][0], qah[ks][1], qah[ks][2], qah[ks][3], bh[u][2], bh[u][3]);
                }
                #pragma unroll
                for (int u = 0; u < 4; ++u) {
                    mma_f16(s[2 * u],     qah[ks][0], qah[ks][1], qah[ks][2], qah[ks][3], bl[u][0], bl[u][1]);
                    mma_f16(s[2 * u + 1], qah[ks][0], qah[ks][1], qah[ks][2], qah[ks][3], bl[u][2], bl[u][3]);
                }
                #pragma unroll
                for (int u = 0; u < 4; ++u) {
                    mma_f16(s[2 * u],     qal[ks][0], qal[ks][1], qal[ks][2], qal[ks][3], bh[u][0], bh[u][1]);
                    mma_f16(s[2 * u + 1], qal[ks][0], qal[ks][1], qal[ks][2], qal[ks][3], bh[u][2], bh[u][3]);
                }
            }

            // ---- issue prefetch of next stage ----
            if (kb + 1 < kv1) {
                const uint32_t nb = sb + (uint32_t)((kb + 1) & 1) * ST_B;
                #pragma unroll
                for (int p = 0; p < 8; ++p) {
                    int vec = t + 128 * p;
                    int row = vec >> 4;
                    int cv  = vec & 15;
                    const size_t g = (size_t)((kb + 1) * 64 + row) * HD + cv * 8;
                    cp16(nb + ST_KH + (uint32_t)row * QSTRB + cv * 16, kh + g);
                    cp16(nb + ST_KL + (uint32_t)row * QSTRB + cv * 16, kl + g);
                    cp16(nb + ST_V  + (uint32_t)row * VSTRB + cv * 16, vv + g);
                }
                cp_commit();
            }

            // causal mask on diagonal block
            if (kb == qb) {
                #pragma unroll
                for (int n = 0; n < 8; ++n) {
                    int c0 = n * 8 + 2 * (l & 3);
                    if (c0     > rA) s[n][0] = -1e30f;
                    if (c0 + 1 > rA) s[n][1] = -1e30f;
                    if (c0     > rB) s[n][2] = -1e30f;
                    if (c0 + 1 > rB) s[n][3] = -1e30f;
                }
            }

            // ---- online softmax (exp2 domain, f16x2 MUFU) ----
            float mxA = s[0][0], mxB = s[0][2];
            #pragma unroll
            for (int n = 0; n < 8; ++n) {
                mxA = fmaxf(mxA, fmaxf(s[n][0], s[n][1]));
                mxB = fmaxf(mxB, fmaxf(s[n][2], s[n][3]));
            }
            mxA = fmaxf(mxA, __shfl_xor_sync(0xffffffffu, mxA, 1));
            mxA = fmaxf(mxA, __shfl_xor_sync(0xffffffffu, mxA, 2));
            mxB = fmaxf(mxB, __shfl_xor_sync(0xffffffffu, mxB, 1));
            mxB = fmaxf(mxB, __shfl_xor_sync(0xffffffffu, mxB, 2));
            const float nmA = fmaxf(mA, mxA);
            const float nmB = fmaxf(mB, mxB);

            uint32_t pA[8], pB[8];
            #pragma unroll
            for (int n = 0; n < 8; ++n) {
                pA[n] = h2ex2(packh2(s[n][0] - nmA, s[n][1] - nmA));
                pB[n] = h2ex2(packh2(s[n][2] - nmB, s[n][3] - nmB));
            }

            if (nmA > mA) {
                float aA = ex2f(mA - nmA);
                #pragma unroll
                for (int i = 0; i < 17; ++i) { o[i][0] *= aA; o[i][1] *= aA; }
                mA = nmA;
            }
            if (nmB > mB) {
                float aB = ex2f(mB - nmB);
                #pragma unroll
                for (int i = 0; i < 17; ++i) { o[i][2] *= aB; o[i][3] *= aB; }
                mB = nmB;
            }

            // ---- O += P V: batched ldsm per kt ----
            #pragma unroll
            for (int kt = 0; kt < 4; ++kt) {
                uint32_t a0 = pA[2 * kt], a1 = pB[2 * kt];
                uint32_t a2 = pA[2 * kt + 1], a3 = pB[2 * kt + 1];
                uint32_t vb[9][4];
                #pragma unroll
                for (int u = 0; u < 9; ++u) {
                    uint32_t off = (uint32_t)(kt * 16) * VSTRB + vb_row + u * 32 + vb_col;
                    ldsm4t(vb[u], cb + ST_V + off);
                }
                #pragma unroll
                for (int u = 0; u < 9; ++u) {
                    mma_f16(o[2 * u],     a0, a1, a2, a3, vb[u][0], vb[u][1]);
                    mma_f16(o[2 * u + 1], a0, a1, a2, a3, vb[u][2], vb[u][3]);
                }
            }
            __syncthreads();
        }

        // ---- epilogue: write unnormalized partial + stats ----
        float (*po)[HD] = g_po[task];
        #pragma unroll
        for (int n = 0; n < 16; ++n) {
            int c = n * 8 + 2 * (l & 3);
            float2 vA, vB;
            vA.x = o[n][0]; vA.y = o[n][1];
            vB.x = o[n][2]; vB.y = o[n][3];
            *(float2*)(&po[rA][c]) = vA;
            *(float2*)(&po[rB][c]) = vB;
        }
        if ((l & 3) == 0) {
            g_pml[task][rA][0] = mA;
            g_pml[task][rA][1] = o[16][0];
            g_pml[task][rB][0] = mB;
            g_pml[task][rB][1] = o[16][2];
        }
    }
}

// =====================================================================
// Kernel 3: merge partials.  grid (64, 4) = (qb, b); 256 threads.
// out[r][c] = cf/L * sum_i 2^(m_i - M) * o_i[r][c]
// =====================================================================
__global__ void merge_kernel(float* __restrict__ outp)
{
    const int qb = blockIdx.x;
    const int b  = blockIdx.y;
    const int nch = (qb >> 3) + 1;
    const int t = threadIdx.x;

    __shared__ float wsh[8][64];
    __shared__ float ssc[64];

    // base slot for this (qb): tasks enumerated qb=63 downward
    int base = 0;
    for (int q = 63; q > qb; --q) base += 4 * ((q >> 3) + 1);

    if (t < 64) {
        float m[8], lv[8];
        float M = -1e30f;
        for (int i = 0; i < nch; ++i) {
            int slot = base + 4 * i + b;
            m[i]  = g_pml[slot][t][0];
            lv[i] = g_pml[slot][t][1];
            M = fmaxf(M, m[i]);
        }
        float L = 0.f;
        for (int i = 0; i < nch; ++i) {
            float wi = ex2f(m[i] - M);
            wsh[i][t] = wi;
            L += wi * lv[i];
        }
        ssc[t] = 0.0883883476483184406f / L;   // 1/sqrt(128) / L
    }
    __syncthreads();

    float* op = outp + ((size_t)b * S_LEN + qb * 64) * HD;
    for (int e = t; e < 64 * HD; e += 256) {
        int r = e >> 7;
        int c = e & 127;
        float acc = 0.f;
        for (int i = 0; i < nch; ++i) {
            int slot = base + 4 * i + b;
            acc += wsh[i][r] * g_po[slot][r][c];
        }
        op[(size_t)r * HD + c] = acc * ssc[r];
    }
}

// =====================================================================
extern "C" void kernel_launch(void* const* d_in, const int* in_sizes, int n_in,
                              void* d_out, int out_size)
{
    const float* x  = (const float*)d_in[0];
    const float* Wq = (const float*)d_in[1];
    const float* bq = (const float*)d_in[2];
    const float* Wk = (const float*)d_in[3];
    const float* bk = (const float*)d_in[4];
    const float* Wv = (const float*)d_in[5];
    const float* bv = (const float*)d_in[6];
    float* out = (float*)d_out;

    convert_x_kernel<<<8192, 256>>>(x);
    convert_w_kernel<<<1024, 256>>>(Wq, Wk, Wv);

    cudaFuncSetAttribute(proj_mma_kernel,
                         cudaFuncAttributeMaxDynamicSharedMemorySize, PJ_SM_TOT);
    dim3 pg(3, 128);
    proj_mma_kernel<<<pg, 256, PJ_SM_TOT>>>(bq, bk, bv);

    cudaFuncSetAttribute(attn_kernel,
                         cudaFuncAttributeMaxDynamicSharedMemorySize, SM_ATT_TOT);
    attn_kernel<<<296, 128, SM_ATT_TOT>>>();

    dim3 mg(64, NB);
    merge_kernel<<<mg, 256>>>(out);
}